// round 5
// baseline (speedup 1.0000x reference)
#include <cuda_runtime.h>
#include <cuda_fp16.h>
#include <math.h>
#include <stdint.h>

#define MROWS  16384
#define LSEQ   4096
#define BSZ    4
#define DIMC   384
#define DINNER 768
#define DSTATE 16
#define DTRANK 24

typedef __half h16;

// ---------------- scratch (device globals; allocation-free) ----------------
__device__ h16 g_Wr16  [384*768];     // [N,K] k-major fp16
__device__ h16 g_Win16 [1536*384];
__device__ h16 g_Winb16[768*384];
__device__ h16 g_Winc16[768*384];
__device__ h16 g_Wout16[384*768];
__device__ h16 g_Wxp16 [64*768];      // N=40 padded to 64 (pad rows zeroed)
__device__ h16 g_Wxpc16[64*768];      // N=16 padded to 64
__device__ float g_Wdt_t[24*768];

__device__ h16 g_ms16  [MROWS*384];
__device__ h16 g_pan16 [MROWS*384];
__device__ h16 g_msn16 [MROWS*384];
__device__ h16 g_pann16[MROWS*384];
__device__ h16 g_conn16[MROWS*384];
__device__ h16 g_xb16  [MROWS*768];
__device__ h16 g_xc16  [MROWS*768];
__device__ h16 g_y16   [MROWS*768];

__device__ float g_red [MROWS*384];
__device__ float g_xz  [(size_t)MROWS*1536];
__device__ float g_xbp [MROWS*768];
__device__ float g_xcp [MROWS*768];
__device__ float g_x   [MROWS*768];
__device__ float g_dbl [MROWS*40];
__device__ float g_dt  [MROWS*768];
__device__ float g_cm  [MROWS*16];
__device__ float g_gf  [MROWS*384];
__device__ float g_img [MROWS*384];

// ---------------- helpers ----------------
__device__ __forceinline__ float silu_f(float v) {
    return v / (1.f + __expf(-v));
}
__device__ __forceinline__ void store_act(float* p, float v) { *p = v; }
__device__ __forceinline__ void store_act(h16* p, float v)   { *p = __float2half_rn(v); }

// ---------------- fp32 -> fp16 convert ----------------
__global__ void f2h(const float4* __restrict__ in, __half2* __restrict__ out, int n4) {
    int i = blockIdx.x * blockDim.x + threadIdx.x;
    if (i >= n4) return;
    float4 v = in[i];
    out[i * 2 + 0] = __floats2half2_rn(v.x, v.y);
    out[i * 2 + 1] = __floats2half2_rn(v.z, v.w);
}

// ---------------- zero fp16 range (weight padding) ----------------
__global__ void zero_h(h16* __restrict__ p, int n) {
    int i = blockIdx.x * blockDim.x + threadIdx.x;
    if (i < n) p[i] = __float2half(0.f);
}

// ---------------- weight transpose (dt_proj fp32) ----------------
__global__ void wt_transpose(const float* __restrict__ in, float* __restrict__ out,
                             int N, int K) {
    int idx = blockIdx.x * blockDim.x + threadIdx.x;
    if (idx >= N * K) return;
    int n = idx % N;
    int k = idx / N;
    out[(size_t)k * N + n] = in[(size_t)n * K + k];
}

// ---------------- layernorm over 384 -> fp16 out ----------------
__global__ __launch_bounds__(128) void ln_kernel(const float* __restrict__ x,
                                                 const float* __restrict__ w,
                                                 const float* __restrict__ b,
                                                 h16* __restrict__ out) {
    int m = blockIdx.x;
    int t = threadIdx.x;
    const float* row = x + (size_t)m * 384;
    float v0 = row[t], v1 = row[t + 128], v2 = row[t + 256];
    float s = v0 + v1 + v2;
    __shared__ float red1[4], red2[4];
    #pragma unroll
    for (int o = 16; o; o >>= 1) s += __shfl_xor_sync(0xffffffffu, s, o);
    if ((t & 31) == 0) red1[t >> 5] = s;
    __syncthreads();
    float mu = (red1[0] + red1[1] + red1[2] + red1[3]) * (1.f / 384.f);
    float d0 = v0 - mu, d1 = v1 - mu, d2 = v2 - mu;
    float q = d0 * d0 + d1 * d1 + d2 * d2;
    #pragma unroll
    for (int o = 16; o; o >>= 1) q += __shfl_xor_sync(0xffffffffu, q, o);
    if ((t & 31) == 0) red2[t >> 5] = q;
    __syncthreads();
    float var = (red2[0] + red2[1] + red2[2] + red2[3]) * (1.f / 384.f);
    float inv = rsqrtf(var + 1e-5f);
    h16* o = out + (size_t)m * 384;
    o[t]       = __float2half_rn(d0 * inv * w[t]       + b[t]);
    o[t + 128] = __float2half_rn(d1 * inv * w[t + 128] + b[t + 128]);
    o[t + 256] = __float2half_rn(d2 * inv * w[t + 256] + b[t + 256]);
}

// ---------------- HFMA2 GEMM ----------------
// C[M,N](f32) = A[M,K](f16) @ Bw[N,K](f16)^T (+bias, +resid)
// Tiles: 128 x BN, BK=32 (16 half2 k-steps), 256 threads.
// fp16 pair accumulators promoted to fp32 every 2 k-tiles (64 k's).
template<int BN, int TM>
__global__ __launch_bounds__(256) void gemm_h2(
    const h16* __restrict__ A, int lda,
    const h16* __restrict__ A2, int lda2, int ksplit,
    const h16* __restrict__ Bw, int ldb,
    const float* __restrict__ bias,
    const float* __restrict__ resid, int ldr,
    float* __restrict__ C, int ldc, int Nstore, int K)
{
    __shared__ __half2 As[2][16][128];
    __shared__ __half2 Bs[2][16][BN];
    const int tid = threadIdx.x;
    const int bm = blockIdx.y * 128;
    const int bn = blockIdx.x * BN;
    const int rg = tid / (BN / 8);
    const int cg = tid % (BN / 8);

    const int nkt = K >> 5;

    uint4 aR[2];
    uint4 bR[BN / 64];

    auto fetch = [&](int kt) {
        const int kg = kt * 32;
        const h16* Asrc; int alds, aoff;
        if (A2 != nullptr && kg >= ksplit) { Asrc = A2; alds = lda2; aoff = kg - ksplit; }
        else                               { Asrc = A;  alds = lda;  aoff = kg; }
        #pragma unroll
        for (int i = 0; i < 2; i++) {
            int ch = tid + i * 256;
            int m = ch & 127, kq = (ch >> 7) * 8;
            aR[i] = *(const uint4*)(Asrc + (size_t)(bm + m) * alds + aoff + kq);
        }
        #pragma unroll
        for (int i = 0; i < BN / 64; i++) {
            int ch = tid + i * 256;
            int n = ch & (BN - 1), kq = (ch / BN) * 8;
            bR[i] = *(const uint4*)(Bw + (size_t)(bn + n) * ldb + kg + kq);
        }
    };
    auto stores = [&](int buf) {
        #pragma unroll
        for (int i = 0; i < 2; i++) {
            int ch = tid + i * 256;
            int m = ch & 127, k2 = (ch >> 7) * 4;
            const __half2* s = (const __half2*)&aR[i];
            #pragma unroll
            for (int j = 0; j < 4; j++) As[buf][k2 + j][m] = s[j];
        }
        #pragma unroll
        for (int i = 0; i < BN / 64; i++) {
            int ch = tid + i * 256;
            int n = ch & (BN - 1), k2 = (ch / BN) * 4;
            const __half2* s = (const __half2*)&bR[i];
            #pragma unroll
            for (int j = 0; j < 4; j++) Bs[buf][k2 + j][n] = s[j];
        }
    };

    __half2 acc[TM][8];
    float accf[TM][8];
    #pragma unroll
    for (int i = 0; i < TM; i++)
        #pragma unroll
        for (int j = 0; j < 8; j++) {
            acc[i][j] = __float2half2_rn(0.f);
            accf[i][j] = 0.f;
        }

    fetch(0);
    stores(0);
    if (nkt > 1) fetch(1);
    __syncthreads();

    for (int kt = 0; kt < nkt; ++kt) {
        const int buf = kt & 1;
        #pragma unroll
        for (int k2 = 0; k2 < 16; ++k2) {
            __half2 a[TM], b[8];
            #pragma unroll
            for (int q = 0; q < TM / 4; q++)
                *(uint4*)&a[q * 4] = *(const uint4*)&As[buf][k2][rg * TM + q * 4];
            *(uint4*)&b[0] = *(const uint4*)&Bs[buf][k2][cg * 8];
            *(uint4*)&b[4] = *(const uint4*)&Bs[buf][k2][cg * 8 + 4];
            #pragma unroll
            for (int i = 0; i < TM; i++)
                #pragma unroll
                for (int j = 0; j < 8; j++)
                    acc[i][j] = __hfma2(a[i], b[j], acc[i][j]);
        }
        if ((kt & 1) || kt == nkt - 1) {
            #pragma unroll
            for (int i = 0; i < TM; i++)
                #pragma unroll
                for (int j = 0; j < 8; j++) {
                    float2 f = __half22float2(acc[i][j]);
                    accf[i][j] += f.x + f.y;
                    acc[i][j] = __float2half2_rn(0.f);
                }
        }
        __syncthreads();
        if (kt + 1 < nkt) {
            stores(buf ^ 1);
            if (kt + 2 < nkt) fetch(kt + 2);
            __syncthreads();
        }
    }

    // epilogue
    int n0 = bn + cg * 8;
    if (n0 < Nstore) {
        #pragma unroll
        for (int i = 0; i < TM; i++) {
            int row = bm + rg * TM + i;
            float* crow = C + (size_t)row * ldc + n0;
            #pragma unroll
            for (int j = 0; j < 8; j += 4) {
                float4 v = make_float4(accf[i][j], accf[i][j + 1],
                                       accf[i][j + 2], accf[i][j + 3]);
                if (bias) {
                    const float4 bb = *(const float4*)&bias[n0 + j];
                    v.x += bb.x; v.y += bb.y; v.z += bb.z; v.w += bb.w;
                }
                if (resid) {
                    const float4 rr = *(const float4*)(resid + (size_t)row * ldr + n0 + j);
                    v.x += rr.x; v.y += rr.y; v.z += rr.z; v.w += rr.w;
                }
                *(float4*)(crow + j) = v;
            }
        }
    }
}

// ---------------- fp32 SGEMM (dt_proj: K=24, softplus) ----------------
__global__ __launch_bounds__(256) void sgemm(
    const float* __restrict__ A, int lda,
    const float* __restrict__ Bt,
    const float* __restrict__ bias,
    float* __restrict__ C, int ldc,
    int M, int N, int K, int act)
{
    __shared__ float As[8][132];
    __shared__ float Bs[8][128];
    int tid = threadIdx.x;
    int bm = blockIdx.y * 128, bn = blockIdx.x * 128;
    int row = tid / 16, col = tid % 16;

    float acc[8][8];
    #pragma unroll
    for (int i = 0; i < 8; i++)
        #pragma unroll
        for (int j = 0; j < 8; j++) acc[i][j] = 0.f;

    int a_m = tid / 2;
    int a_k = (tid % 2) * 4;
    int b_n = (tid % 32) * 4;
    int b_k = tid / 32;

    int ktiles = (K + 7) / 8;
    for (int t = 0; t < ktiles; ++t) {
        int k0 = t * 8;
        {
            float4 av = make_float4(0.f, 0.f, 0.f, 0.f);
            int gm = bm + a_m, gk = k0 + a_k;
            const float* ap = A + (size_t)gm * lda;
            if (gk + 3 < K) {
                av = *(const float4*)(ap + gk);
            } else {
                if (gk + 0 < K) av.x = ap[gk + 0];
                if (gk + 1 < K) av.y = ap[gk + 1];
                if (gk + 2 < K) av.z = ap[gk + 2];
                if (gk + 3 < K) av.w = ap[gk + 3];
            }
            As[a_k + 0][a_m] = av.x;
            As[a_k + 1][a_m] = av.y;
            As[a_k + 2][a_m] = av.z;
            As[a_k + 3][a_m] = av.w;
        }
        {
            float4 bvv = make_float4(0.f, 0.f, 0.f, 0.f);
            int gn = bn + b_n, gk = k0 + b_k;
            if (gk < K) {
                const float* bp = Bt + (size_t)gk * N;
                if (gn + 3 < N) {
                    bvv = *(const float4*)(bp + gn);
                } else {
                    if (gn + 0 < N) bvv.x = bp[gn + 0];
                    if (gn + 1 < N) bvv.y = bp[gn + 1];
                    if (gn + 2 < N) bvv.z = bp[gn + 2];
                    if (gn + 3 < N) bvv.w = bp[gn + 3];
                }
            }
            *(float4*)&Bs[b_k][b_n] = bvv;
        }
        __syncthreads();
        #pragma unroll
        for (int k = 0; k < 8; ++k) {
            float a[8], b[8];
            *(float4*)(a)     = *(const float4*)&As[k][row * 8];
            *(float4*)(a + 4) = *(const float4*)&As[k][row * 8 + 4];
            *(float4*)(b)     = *(const float4*)&Bs[k][col * 8];
            *(float4*)(b + 4) = *(const float4*)&Bs[k][col * 8 + 4];
            #pragma unroll
            for (int i = 0; i < 8; i++)
                #pragma unroll
                for (int j = 0; j < 8; j++)
                    acc[i][j] = fmaf(a[i], b[j], acc[i][j]);
        }
        __syncthreads();
    }
    #pragma unroll
    for (int i = 0; i < 8; i++) {
        int m = bm + row * 8 + i;
        if (m >= M) continue;
        #pragma unroll
        for (int j = 0; j < 8; j++) {
            int n = bn + col * 8 + j;
            if (n >= N) continue;
            float v = acc[i][j];
            if (bias) v += bias[n];
            if (act == 1) {
                v = (v > 20.f) ? v : log1pf(expf(v));
            }
            C[(size_t)m * ldc + n] = v;
        }
    }
}

// ---------------- causal depthwise conv1d (K=4) + SiLU ----------------
template<typename OutT>
__global__ void dwconv1d_silu(const float* __restrict__ x, int xstride,
                              const float* __restrict__ w,
                              const float* __restrict__ bias,
                              OutT* __restrict__ out) {
    int idx = blockIdx.x * blockDim.x + threadIdx.x;
    if (idx >= MROWS * DINNER) return;
    int d = idx % DINNER;
    int m = idx / DINNER;
    int l = m & (LSEQ - 1);
    float acc = bias[d];
    #pragma unroll
    for (int k = 0; k < 4; k++) {
        int ll = l - 3 + k;
        if (ll >= 0)
            acc += w[d * 4 + k] * x[(size_t)(m + (ll - l)) * xstride + d];
    }
    store_act(&out[(size_t)m * DINNER + d], silu_f(acc));
}

// ---------------- selective scan (+ fused silu(z) gate), fp16 output ----------------
__global__ __launch_bounds__(256) void scan_kernel(
    const float* __restrict__ u,
    const float* __restrict__ dt,
    const float* __restrict__ dbl,
    const float* __restrict__ Cm,
    const float* __restrict__ A_log,
    const float* __restrict__ Dp,
    const float* __restrict__ xz,
    h16* __restrict__ y)
{
    int b  = blockIdx.x / 48;
    int d0 = (blockIdx.x % 48) * 16;
    int tid = threadIdx.x;
    int dl = tid / 16;
    int n  = tid % 16;
    int d = d0 + dl;
    float a = -expf(A_log[d * 16 + n]);
    float Dv = Dp[d];
    __shared__ float sdt[16][16], su[16][16], sB[16][17], sC[16][17];
    float h = 0.f;
    size_t base = (size_t)b * LSEQ;
    int lo = tid / 16, c = tid % 16;
    for (int l0 = 0; l0 < LSEQ; l0 += 16) {
        size_t m = base + l0 + lo;
        sdt[lo][c] = dt[m * 768 + d0 + c];
        su [lo][c] = u [m * 768 + d0 + c];
        sB [lo][c] = dbl[m * 40 + 24 + c];
        sC [lo][c] = Cm [m * 16 + c];
        __syncthreads();
        #pragma unroll
        for (int s = 0; s < 16; ++s) {
            float dtv = sdt[s][dl];
            float uv  = su [s][dl];
            float Bv  = sB [s][n];
            float Cv  = sC [s][n];
            h = expf(dtv * a) * h + dtv * uv * Bv;
            float p = h * Cv;
            p += __shfl_xor_sync(0xffffffffu, p, 8);
            p += __shfl_xor_sync(0xffffffffu, p, 4);
            p += __shfl_xor_sync(0xffffffffu, p, 2);
            p += __shfl_xor_sync(0xffffffffu, p, 1);
            if (n == 0) {
                size_t mm = base + l0 + s;
                float z = xz[mm * 1536 + 768 + d];
                y[mm * 768 + d] = __float2half_rn((p + uv * Dv) * silu_f(z));
            }
        }
        __syncthreads();
    }
}

// ---------------- (B,L,C) -> (B,C,L) transpose ----------------
__global__ void transpose_LC(const float* __restrict__ in, float* __restrict__ out) {
    __shared__ float t[32][33];
    int bb = blockIdx.z;
    int c0 = blockIdx.x * 32, l0 = blockIdx.y * 32;
    const float* ip = in + (size_t)bb * LSEQ * DIMC;
    float* op = out + (size_t)bb * DIMC * LSEQ;
    int tx = threadIdx.x, ty = threadIdx.y;
    #pragma unroll
    for (int i = 0; i < 32; i += 8)
        t[ty + i][tx] = ip[(size_t)(l0 + ty + i) * DIMC + c0 + tx];
    __syncthreads();
    #pragma unroll
    for (int i = 0; i < 32; i += 8)
        op[(size_t)(c0 + ty + i) * LSEQ + l0 + tx] = t[tx][ty + i];
}

// ---------------- final 3x3 depthwise conv (SAME) on (B,C,64,64) ----------------
__global__ void dwconv3x3(const float* __restrict__ img, const float* __restrict__ w,
                          const float* __restrict__ bias, float* __restrict__ out) {
    int idx = blockIdx.x * blockDim.x + threadIdx.x;
    if (idx >= BSZ * DIMC * 64 * 64) return;
    int wv = idx & 63;
    int h  = (idx >> 6) & 63;
    int c  = (idx >> 12) % DIMC;
    int b  = idx / (DIMC * 4096);
    const float* ip = img + ((size_t)b * DIMC + c) * 4096;
    const float* wc = w + c * 9;
    float acc = bias[c];
    #pragma unroll
    for (int dh = -1; dh <= 1; dh++) {
        int hh = h + dh;
        if (hh < 0 || hh >= 64) continue;
        #pragma unroll
        for (int dw = -1; dw <= 1; dw++) {
            int ww = wv + dw;
            if (ww < 0 || ww >= 64) continue;
            acc += wc[(dh + 1) * 3 + (dw + 1)] * ip[hh * 64 + ww];
        }
    }
    out[idx] = acc;
}

// ---------------- host ----------------
static void launch_h2w(const h16* A, int lda, const h16* A2, int lda2, int ksplit,
                       const h16* Bw, int ldb, const float* bias,
                       const float* resid, int ldr,
                       float* C, int ldc, int M, int N, int K) {
    dim3 grid(N / 128, M / 128);
    gemm_h2<128, 8><<<grid, 256>>>(A, lda, A2, lda2, ksplit, Bw, ldb,
                                   bias, resid, ldr, C, ldc, N, K);
}

extern "C" void kernel_launch(void* const* d_in, const int* in_sizes, int n_in,
                              void* d_out, int out_size) {
    const float* ms          = (const float*)d_in[0];
    const float* pan         = (const float*)d_in[1];
    const float* reduce_W    = (const float*)d_in[2];
    const float* reduce_b    = (const float*)d_in[3];
    const float* ln1_w       = (const float*)d_in[4];
    const float* ln1_b       = (const float*)d_in[5];
    const float* ln2_w       = (const float*)d_in[6];
    const float* ln2_b       = (const float*)d_in[7];
    const float* ln3_w       = (const float*)d_in[8];
    const float* ln3_b       = (const float*)d_in[9];
    const float* in_proj_W   = (const float*)d_in[10];
    const float* in_proj_b_W = (const float*)d_in[11];
    const float* in_proj_c_W = (const float*)d_in[12];
    const float* conv_w      = (const float*)d_in[13];
    const float* conv_bias   = (const float*)d_in[14];
    const float* conv_b_w    = (const float*)d_in[15];
    const float* conv_b_bias = (const float*)d_in[16];
    const float* conv_c_w    = (const float*)d_in[17];
    const float* conv_c_bias = (const float*)d_in[18];
    const float* x_proj_W    = (const float*)d_in[19];
    const float* x_proj_c_W  = (const float*)d_in[20];
    const float* dt_proj_W   = (const float*)d_in[21];
    const float* dt_proj_bias= (const float*)d_in[22];
    const float* A_log       = (const float*)d_in[23];
    const float* Dvec        = (const float*)d_in[24];
    const float* out_proj_W  = (const float*)d_in[25];
    const float* dwconv_w    = (const float*)d_in[26];
    const float* dwconv_b    = (const float*)d_in[27];
    float* out = (float*)d_out;

    h16 *pWr16, *pWin16, *pWinb16, *pWinc16, *pWout16, *pWxp16, *pWxpc16;
    h16 *pms16, *ppan16, *pmsn16, *ppann16, *pconn16, *pxb16, *pxc16, *py16;
    float *pWdt, *pred, *pxz, *pxbp, *pxcp, *px, *pdbl, *pdt, *pcm, *pgf, *pimg;
    cudaGetSymbolAddress((void**)&pWr16,   g_Wr16);
    cudaGetSymbolAddress((void**)&pWin16,  g_Win16);
    cudaGetSymbolAddress((void**)&pWinb16, g_Winb16);
    cudaGetSymbolAddress((void**)&pWinc16, g_Winc16);
    cudaGetSymbolAddress((void**)&pWout16, g_Wout16);
    cudaGetSymbolAddress((void**)&pWxp16,  g_Wxp16);
    cudaGetSymbolAddress((void**)&pWxpc16, g_Wxpc16);
    cudaGetSymbolAddress((void**)&pms16,   g_ms16);
    cudaGetSymbolAddress((void**)&ppan16,  g_pan16);
    cudaGetSymbolAddress((void**)&pmsn16,  g_msn16);
    cudaGetSymbolAddress((void**)&ppann16, g_pann16);
    cudaGetSymbolAddress((void**)&pconn16, g_conn16);
    cudaGetSymbolAddress((void**)&pxb16,   g_xb16);
    cudaGetSymbolAddress((void**)&pxc16,   g_xc16);
    cudaGetSymbolAddress((void**)&py16,    g_y16);
    cudaGetSymbolAddress((void**)&pWdt,    g_Wdt_t);
    cudaGetSymbolAddress((void**)&pred,    g_red);
    cudaGetSymbolAddress((void**)&pxz,     g_xz);
    cudaGetSymbolAddress((void**)&pxbp,    g_xbp);
    cudaGetSymbolAddress((void**)&pxcp,    g_xcp);
    cudaGetSymbolAddress((void**)&px,      g_x);
    cudaGetSymbolAddress((void**)&pdbl,    g_dbl);
    cudaGetSymbolAddress((void**)&pdt,     g_dt);
    cudaGetSymbolAddress((void**)&pcm,     g_cm);
    cudaGetSymbolAddress((void**)&pgf,     g_gf);
    cudaGetSymbolAddress((void**)&pimg,    g_img);

    auto cvt = [](const float* in, h16* o, int n) {
        int n4 = n / 4;
        f2h<<<(n4 + 255) / 256, 256>>>((const float4*)in, (__half2*)o, n4);
    };

    // 1-5 (launch 6 = in_proj HFMA2 GEMM for ncu)
    cvt(ms,  pms16,  MROWS * 384);                        // 1
    cvt(pan, ppan16, MROWS * 384);                        // 2
    cvt(in_proj_W, pWin16, 1536 * 384);                   // 3
    ln_kernel<<<MROWS, 128>>>(ms, ln1_w, ln1_b, pmsn16);  // 4
    cvt(reduce_W, pWr16, 384 * 768);                      // 5

    // 6: in_proj GEMM
    launch_h2w(pmsn16, 384, nullptr, 0, 1 << 30, pWin16, 384,
               nullptr, nullptr, 0, pxz, 1536, MROWS, 1536, 384);

    ln_kernel<<<MROWS, 128>>>(pan, ln2_w, ln2_b, ppann16);

    // reduce GEMM with fused concat (A = [ms16 | pan16])
    launch_h2w(pms16, 384, ppan16, 384, 384, pWr16, 768,
               reduce_b, nullptr, 0, pred, 384, MROWS, 384, 768);

    ln_kernel<<<MROWS, 128>>>(pred, ln3_w, ln3_b, pconn16);

    cvt(in_proj_b_W, pWinb16, 768 * 384);
    cvt(in_proj_c_W, pWinc16, 768 * 384);
    cvt(out_proj_W,  pWout16, 384 * 768);
    cvt(x_proj_W,    pWxp16,  40 * 768);
    cvt(x_proj_c_W,  pWxpc16, 16 * 768);
    zero_h<<<(24 * 768 + 255) / 256, 256>>>(pWxp16  + 40 * 768, 24 * 768);
    zero_h<<<(48 * 768 + 255) / 256, 256>>>(pWxpc16 + 16 * 768, 48 * 768);

    launch_h2w(ppann16, 384, nullptr, 0, 1 << 30, pWinb16, 384,
               nullptr, nullptr, 0, pxbp, 768, MROWS, 768, 384);
    launch_h2w(pconn16, 384, nullptr, 0, 1 << 30, pWinc16, 384,
               nullptr, nullptr, 0, pxcp, 768, MROWS, 768, 384);

    // depthwise causal convs + SiLU
    {
        int tot = MROWS * DINNER;
        int blocks = (tot + 255) / 256;
        dwconv1d_silu<float><<<blocks, 256>>>(pxz,  1536, conv_w,   conv_bias,   px);
        dwconv1d_silu<h16>  <<<blocks, 256>>>(pxbp, 768,  conv_b_w, conv_b_bias, pxb16);
        dwconv1d_silu<h16>  <<<blocks, 256>>>(pxcp, 768,  conv_c_w, conv_c_bias, pxc16);
    }

    // narrow projections (HFMA2, BN=64, padded weights)
    gemm_h2<64, 4><<<dim3(1, MROWS / 128), 256>>>(
        pxb16, 768, nullptr, 0, 1 << 30, pWxp16, 768,
        nullptr, nullptr, 0, pdbl, 40, 40, 768);
    gemm_h2<64, 4><<<dim3(1, MROWS / 128), 256>>>(
        pxc16, 768, nullptr, 0, 1 << 30, pWxpc16, 768,
        nullptr, nullptr, 0, pcm, 16, 16, 768);

    // dt_proj (fp32, K=24, softplus)
    wt_transpose<<<(768 * 24 + 255) / 256, 256>>>(dt_proj_W, pWdt, 768, 24);
    {
        dim3 g3(6, MROWS / 128);
        sgemm<<<g3, 256>>>(pdbl, 40, pWdt, dt_proj_bias, pdt, 768, MROWS, 768, 24, 1);
    }

    // selective scan with fused gate -> fp16 y
    scan_kernel<<<BSZ * 48, 256>>>(px, pdt, pdbl, pcm, A_log, Dvec, pxz, py16);

    // out_proj + residual(ms)
    launch_h2w(py16, 768, nullptr, 0, 1 << 30, pWout16, 768,
               nullptr, ms, 384, pgf, 384, MROWS, 384, 768);

    // (B,L,C) -> (B,C,HW) transpose, then 3x3 depthwise conv
    {
        dim3 grid(DIMC / 32, LSEQ / 32, BSZ);
        dim3 blk(32, 8);
        transpose_LC<<<grid, blk>>>(pgf, pimg);
    }
    {
        int tot = BSZ * DIMC * 64 * 64;
        dwconv3x3<<<(tot + 255) / 256, 256>>>(pimg, dwconv_w, dwconv_b, out);
    }
}